// round 1
// baseline (speedup 1.0000x reference)
#include <cuda_runtime.h>
#include <cuda_fp16.h>
#include <cstdint>

#define TOKENS 256
#define INF    4096
#define OUTF   11008
#define GROUP  128
#define QZC    (OUTF/8)     // 1376 packed-zero cols

#define BM 128
#define BN 64
#define BK 32
#define LDA (BK + 8)        // padded row stride in halves (80B, 16B-aligned)

// Scratch: fp16 split of x (hi + lo). 2 x 2MB static device arrays (allowed).
__device__ __half g_xhi[TOKENS * INF];
__device__ __half g_xlo[TOKENS * INF];

__global__ void split_x_kernel(const float* __restrict__ x) {
    int i = blockIdx.x * blockDim.x + threadIdx.x;
    if (i < TOKENS * INF) {
        float v = x[i];
        __half h = __float2half_rn(v);
        g_xhi[i] = h;
        g_xlo[i] = __float2half_rn(v - __half2float(h));
    }
}

__device__ __forceinline__ void mma16816(float* c,
    uint32_t a0, uint32_t a1, uint32_t a2, uint32_t a3,
    uint32_t b0, uint32_t b1)
{
    asm volatile(
        "mma.sync.aligned.m16n8k16.row.col.f32.f16.f16.f32 "
        "{%0,%1,%2,%3}, {%4,%5,%6,%7}, {%8,%9}, {%0,%1,%2,%3};\n"
        : "+f"(c[0]), "+f"(c[1]), "+f"(c[2]), "+f"(c[3])
        : "r"(a0), "r"(a1), "r"(a2), "r"(a3), "r"(b0), "r"(b1));
}

__global__ __launch_bounds__(256, 2)
void gptq_gemm_kernel(const uint32_t* __restrict__ qweight,
                      const uint32_t* __restrict__ qzeros,
                      const float*    __restrict__ scales,
                      const float*    __restrict__ bias,
                      float*          __restrict__ out)
{
    __shared__ __half Ahi[BM * LDA];
    __shared__ __half Alo[BM * LDA];
    __shared__ __half Bs [BN * LDA];   // stored [n][k] so frag loads are contiguous b32

    const int tid = threadIdx.x;
    const int m0 = blockIdx.y * BM;
    const int n0 = blockIdx.x * BN;

    const int warp = tid >> 5, lane = tid & 31;
    const int wm = warp & 3;        // 4 warps along M (32 rows each)
    const int wn = warp >> 2;       // 2 warps along N (32 cols each)
    const int gId = lane >> 2;      // 0..7
    const int t4  = lane & 3;       // 0..3

    // B-dequant mapping: one packed int32 per thread per K-tile
    const int br = tid >> 6;        // which qweight row of the 4 in this K-tile
    const int bc = tid & 63;        // n within tile
    const int n_g = n0 + bc;
    const int zshift = (n_g & 7) * 4;

    float acc[2][4][4];
    #pragma unroll
    for (int i = 0; i < 2; i++)
        #pragma unroll
        for (int j = 0; j < 4; j++)
            #pragma unroll
            for (int r = 0; r < 4; r++) acc[i][j][r] = 0.f;

    for (int kt = 0; kt < INF / BK; kt++) {
        const int k0 = kt * BK;

        // ---- Load A tiles (hi + lo): 128x32 halves each, 16B vectors ----
        #pragma unroll
        for (int v = 0; v < 2; v++) {
            int idx = tid + v * 256;          // 512 uint4 per buffer
            int row = idx >> 2;
            int c16 = (idx & 3) * 8;
            const int goff = (m0 + row) * INF + k0 + c16;
            *(uint4*)&Ahi[row * LDA + c16] = *(const uint4*)&g_xhi[goff];
            *(uint4*)&Alo[row * LDA + c16] = *(const uint4*)&g_xlo[goff];
        }

        // ---- Dequant B tile: int4 -> fp16, [n][k] layout ----
        {
            const int g = k0 >> 7;   // group index (k0..k0+31 stay in one group)
            uint32_t q = qweight[(size_t)((k0 >> 3) + br) * OUTF + n_g];
            float z = (float)(((qzeros[g * QZC + (n_g >> 3)] >> zshift) & 15u) + 1u);
            float s = scales[g * OUTF + n_g];
            float zs = -z * s;       // val = w*s + zs
            __half2 pk[4];
            #pragma unroll
            for (int j = 0; j < 4; j++) {
                float w0 = (float)((q >> (8 * j)) & 15u);
                float w1 = (float)((q >> (8 * j + 4)) & 15u);
                pk[j] = __floats2half2_rn(fmaf(w0, s, zs), fmaf(w1, s, zs));
            }
            *(uint4*)&Bs[bc * LDA + br * 8] = *(const uint4*)pk;
        }

        __syncthreads();

        // ---- MMA over the K-tile: 2 k16 steps x {hi,lo} ----
        #pragma unroll
        for (int kk = 0; kk < 2; kk++) {
            const int kb = kk * 16 + t4 * 2;

            uint32_t b0[4], b1[4];
            #pragma unroll
            for (int j = 0; j < 4; j++) {
                const __half* bp = &Bs[(wn * 32 + j * 8 + gId) * LDA + kb];
                b0[j] = *(const uint32_t*)bp;
                b1[j] = *(const uint32_t*)(bp + 8);
            }

            #pragma unroll
            for (int sel = 0; sel < 2; sel++) {
                const __half* Ab = sel ? Alo : Ahi;
                #pragma unroll
                for (int i = 0; i < 2; i++) {
                    const __half* ap = &Ab[(wm * 32 + i * 16 + gId) * LDA + kb];
                    uint32_t a0 = *(const uint32_t*)ap;
                    uint32_t a1 = *(const uint32_t*)(ap + 8 * LDA);
                    uint32_t a2 = *(const uint32_t*)(ap + 8);
                    uint32_t a3 = *(const uint32_t*)(ap + 8 * LDA + 8);
                    #pragma unroll
                    for (int j = 0; j < 4; j++)
                        mma16816(acc[i][j], a0, a1, a2, a3, b0[j], b1[j]);
                }
            }
        }

        __syncthreads();
    }

    // ---- Epilogue: add bias, store fp32 ----
    #pragma unroll
    for (int i = 0; i < 2; i++) {
        int mrow = m0 + wm * 32 + i * 16 + gId;
        #pragma unroll
        for (int j = 0; j < 4; j++) {
            int ncol = n0 + wn * 32 + j * 8 + t4 * 2;
            float2 bb = *(const float2*)&bias[ncol];
            float2 r0 = make_float2(acc[i][j][0] + bb.x, acc[i][j][1] + bb.y);
            float2 r1 = make_float2(acc[i][j][2] + bb.x, acc[i][j][3] + bb.y);
            *(float2*)&out[(size_t)mrow * OUTF + ncol] = r0;
            *(float2*)&out[(size_t)(mrow + 8) * OUTF + ncol] = r1;
        }
    }
}

extern "C" void kernel_launch(void* const* d_in, const int* in_sizes, int n_in,
                              void* d_out, int out_size)
{
    const float*    x       = (const float*)d_in[0];
    const uint32_t* qweight = (const uint32_t*)d_in[1];
    const uint32_t* qzeros  = (const uint32_t*)d_in[2];
    const float*    scales  = (const float*)d_in[3];
    const float*    bias    = (const float*)d_in[4];
    float* out = (float*)d_out;

    split_x_kernel<<<(TOKENS * INF + 255) / 256, 256>>>(x);

    dim3 grid(OUTF / BN, TOKENS / BM);   // 172 x 2
    gptq_gemm_kernel<<<grid, 256>>>(qweight, qzeros, scales, bias, out);
}

// round 5
// speedup vs baseline: 2.3015x; 2.3015x over previous
#include <cuda_runtime.h>
#include <cuda_fp16.h>
#include <cstdint>

#define TOKENS 256
#define INF    4096
#define OUTF   11008
#define QZC    (OUTF/8)

#define BM 128
#define BN 64
#define BK 64
#define LDA 72          // halves, 144B row stride (16B aligned, LDSM conflict-free)
#define LDB 72
#define SPLITK 4
#define KSLICE (INF/SPLITK)   // 1024
#define NT (KSLICE/BK)        // 16

// fp16 copy of x
__device__ __half g_xh[TOKENS * INF];

__global__ void split_x_kernel(const float* __restrict__ x) {
    int i = blockIdx.x * blockDim.x + threadIdx.x;
    if (i < TOKENS * INF) g_xh[i] = __float2half_rn(x[i]);
}

__global__ void init_out_kernel(const float* __restrict__ bias, float* __restrict__ out) {
    int i = blockIdx.x * blockDim.x + threadIdx.x;     // over TOKENS*OUTF/4
    if (i < TOKENS * OUTF / 4) {
        int c4 = i % (OUTF / 4);
        ((float4*)out)[i] = ((const float4*)bias)[c4];
    }
}

__device__ __forceinline__ void cp16(void* smem, const void* gmem) {
    uint32_t s = (uint32_t)__cvta_generic_to_shared(smem);
    asm volatile("cp.async.cg.shared.global [%0], [%1], 16;\n" :: "r"(s), "l"(gmem));
}
__device__ __forceinline__ void cp_commit() {
    asm volatile("cp.async.commit_group;\n" ::: "memory");
}
__device__ __forceinline__ void cp_wait_all() {
    asm volatile("cp.async.wait_group 0;\n" ::: "memory");
}

__device__ __forceinline__ void ldsm_x4(uint32_t* r, uint32_t addr) {
    asm volatile("ldmatrix.sync.aligned.m8n8.x4.shared.b16 {%0,%1,%2,%3}, [%4];\n"
                 : "=r"(r[0]), "=r"(r[1]), "=r"(r[2]), "=r"(r[3]) : "r"(addr));
}
__device__ __forceinline__ void ldsm_x2(uint32_t* r, uint32_t addr) {
    asm volatile("ldmatrix.sync.aligned.m8n8.x2.shared.b16 {%0,%1}, [%2];\n"
                 : "=r"(r[0]), "=r"(r[1]) : "r"(addr));
}

__device__ __forceinline__ void mma16816(float* c,
    const uint32_t* a, uint32_t b0, uint32_t b1)
{
    asm volatile(
        "mma.sync.aligned.m16n8k16.row.col.f32.f16.f16.f32 "
        "{%0,%1,%2,%3}, {%4,%5,%6,%7}, {%8,%9}, {%0,%1,%2,%3};\n"
        : "+f"(c[0]), "+f"(c[1]), "+f"(c[2]), "+f"(c[3])
        : "r"(a[0]), "r"(a[1]), "r"(a[2]), "r"(a[3]), "r"(b0), "r"(b1));
}

extern __shared__ __half smem_raw[];

__global__ __launch_bounds__(256, 2)
void gptq_gemm_kernel(const uint32_t* __restrict__ qweight,
                      const uint32_t* __restrict__ qzeros,
                      const float*    __restrict__ scales,
                      float*          __restrict__ out)
{
    __half* Ab[2] = { smem_raw, smem_raw + BM * LDA };
    __half* Bb[2] = { smem_raw + 2 * BM * LDA, smem_raw + 2 * BM * LDA + BN * LDB };

    const int tid  = threadIdx.x;
    const int m0   = blockIdx.y * BM;
    const int n0   = blockIdx.x * BN;
    const int kbase = blockIdx.z * KSLICE;

    const int warp = tid >> 5, lane = tid & 31;
    const int wm = warp & 3;     // 4 warps over M (32 rows each)
    const int wn = warp >> 2;    // 2 warps over N (32 cols each)

    // ---- B dequant mapping: 2 packed words per thread per K-tile ----
    const int bc  = tid & 63;          // n within tile
    const int br0 = tid >> 6;          // word-rows br0, br0+4 (of 8)
    const int n_g = n0 + bc;
    const int zshift = (n_g & 7) * 4;

    // ---- ldmatrix per-lane addresses ----
    const int mi  = lane >> 3;
    const int r_a = (lane & 7) + (mi & 1) * 8;
    const int k_a = (mi >> 1) * 8;
    const int r_b = lane & 7;
    const int k_b = (mi & 1) * 8;

    uint32_t aAddr[2][2], bAddr[2][4];
    #pragma unroll
    for (int p = 0; p < 2; p++) {
        uint32_t ab = (uint32_t)__cvta_generic_to_shared(Ab[p]);
        uint32_t bb = (uint32_t)__cvta_generic_to_shared(Bb[p]);
        #pragma unroll
        for (int i = 0; i < 2; i++)
            aAddr[p][i] = ab + 2u * ((wm * 32 + i * 16 + r_a) * LDA + k_a);
        #pragma unroll
        for (int j = 0; j < 4; j++)
            bAddr[p][j] = bb + 2u * ((wn * 32 + j * 8 + r_b) * LDB + k_b);
    }

    float acc[2][4][4];
    #pragma unroll
    for (int i = 0; i < 2; i++)
        #pragma unroll
        for (int j = 0; j < 4; j++)
            #pragma unroll
            for (int r = 0; r < 4; r++) acc[i][j][r] = 0.f;

    uint32_t qw[2][2];
    float ss[2], zz[2];

    auto load_q = [&](int t, int p) {
        const int k0 = kbase + t * BK;
        const int g  = k0 >> 7;
        qw[p][0] = qweight[(size_t)((k0 >> 3) + br0)     * OUTF + n_g];
        qw[p][1] = qweight[(size_t)((k0 >> 3) + br0 + 4) * OUTF + n_g];
        float s = scales[g * OUTF + n_g];
        float z = (float)(((qzeros[g * QZC + (n_g >> 3)] >> zshift) & 15u) + 1u);
        ss[p] = s; zz[p] = -z * s;
    };

    auto dequant_store = [&](int p) {
        const float s = ss[p], zs = zz[p];
        #pragma unroll
        for (int w = 0; w < 2; w++) {
            const uint32_t q = qw[p][w];
            __half2 pk[4];
            #pragma unroll
            for (int j = 0; j < 4; j++) {
                float w0 = (float)((q >> (8 * j)) & 15u);
                float w1 = (float)((q >> (8 * j + 4)) & 15u);
                pk[j] = __floats2half2_rn(fmaf(w0, s, zs), fmaf(w1, s, zs));
            }
            *(uint4*)&Bb[p][bc * LDB + (br0 + 4 * w) * 8] = *(const uint4*)pk;
        }
    };

    auto cpasync_A = [&](int t, int p) {
        const int k0 = kbase + t * BK;
        #pragma unroll
        for (int v = 0; v < 4; v++) {
            int idx = tid + v * 256;
            int row = idx >> 3;
            int c   = (idx & 7) * 8;
            cp16(&Ab[p][row * LDA + c], &g_xh[(m0 + row) * INF + k0 + c]);
        }
    };

    // ---- prologue ----
    cpasync_A(0, 0);
    cp_commit();
    load_q(0, 0);
    dequant_store(0);
    load_q(1, 1);

    // ---- mainloop ----
    #pragma unroll 2
    for (int t = 0; t < NT; t++) {
        const int p = t & 1;
        cp_wait_all();
        __syncthreads();

        if (t + 1 < NT) { cpasync_A(t + 1, p ^ 1); cp_commit(); }

        #pragma unroll
        for (int kk = 0; kk < 4; kk++) {
            uint32_t a[2][4];
            #pragma unroll
            for (int i = 0; i < 2; i++) ldsm_x4(a[i], aAddr[p][i] + kk * 32);
            uint32_t b[4][2];
            #pragma unroll
            for (int j = 0; j < 4; j++) ldsm_x2(b[j], bAddr[p][j] + kk * 32);
            #pragma unroll
            for (int i = 0; i < 2; i++)
                #pragma unroll
                for (int j = 0; j < 4; j++)
                    mma16816(acc[i][j], a[i], b[j][0], b[j][1]);
        }

        if (t + 1 < NT) dequant_store(p ^ 1);
        if (t + 2 < NT) load_q(t + 2, p);
    }

    // ---- epilogue: atomic accumulate (out pre-set to bias) ----
    const int gId = lane >> 2;
    const int t4  = lane & 3;
    #pragma unroll
    for (int i = 0; i < 2; i++) {
        int mrow = m0 + wm * 32 + i * 16 + gId;
        #pragma unroll
        for (int j = 0; j < 4; j++) {
            int ncol = n0 + wn * 32 + j * 8 + t4 * 2;
            atomicAdd(&out[(size_t)mrow * OUTF + ncol],           acc[i][j][0]);
            atomicAdd(&out[(size_t)mrow * OUTF + ncol + 1],       acc[i][j][1]);
            atomicAdd(&out[(size_t)(mrow + 8) * OUTF + ncol],     acc[i][j][2]);
            atomicAdd(&out[(size_t)(mrow + 8) * OUTF + ncol + 1], acc[i][j][3]);
        }
    }
}

extern "C" void kernel_launch(void* const* d_in, const int* in_sizes, int n_in,
                              void* d_out, int out_size)
{
    const float*    x       = (const float*)d_in[0];
    const uint32_t* qweight = (const uint32_t*)d_in[1];
    const uint32_t* qzeros  = (const uint32_t*)d_in[2];
    const float*    scales  = (const float*)d_in[3];
    const float*    bias    = (const float*)d_in[4];
    float* out = (float*)d_out;

    const int smem_bytes = (2 * BM * LDA + 2 * BN * LDB) * (int)sizeof(__half); // 55296
    static bool attr_done = false;
    if (!attr_done) {
        cudaFuncSetAttribute(gptq_gemm_kernel,
                             cudaFuncAttributeMaxDynamicSharedMemorySize, smem_bytes);
        attr_done = true;
    }

    split_x_kernel<<<(TOKENS * INF + 255) / 256, 256>>>(x);
    init_out_kernel<<<(TOKENS * OUTF / 4 + 255) / 256, 256>>>(bias, out);

    dim3 grid(OUTF / BN, TOKENS / BM, SPLITK);   // 172 x 2 x 4 = 1376 CTAs
    gptq_gemm_kernel<<<grid, 256, smem_bytes>>>(qweight, qzeros, scales, out);
}